// round 2
// baseline (speedup 1.0000x reference)
#include <cuda_runtime.h>

// Problem constants
#define TT 50176          // 2*128*196 tokens
#define DD 1024           // d_model
#define EE 2048           // d_inner
#define NS 8              // d_state
#define EPS 1e-5f

// Tiling
#define BT 128            // tokens per block
#define BE 128            // d_inner tile
#define BK 32             // k chunk
#define NTHREADS 256
#define XSTR (BT + 4)     // 132, keeps float4 alignment, breaks systematic conflicts
#define WSTR (BE + 4)

// smem layout (float offsets)
#define OFF_MU    0
#define OFF_RSTD  (OFF_MU + BT)
#define OFF_SU    (OFF_RSTD + BT)            // BT*NS = 1024
#define OFF_GAMMA (OFF_SU + BT * NS)
#define OFF_BETA  (OFF_GAMMA + DD)
#define OFF_XS    (OFF_BETA + DD)            // 2*BK*XSTR = 8448
#define OFF_WS    (OFF_XS + 2 * BK * XSTR)   // 2*BK*WSTR = 8448
#define SMEM_FLOATS (OFF_WS + 2 * BK * WSTR) // 20224 floats = 80896 bytes

__device__ __forceinline__ float silu_f(float v) {
    return v * (1.0f / (1.0f + __expf(-v)));
}

__device__ __forceinline__ void stage_ldg(const float* __restrict__ xblk,
                                          const float* __restrict__ wblk,
                                          int srow, int skh, int kc,
                                          float4 rx[4], float4 rw[4]) {
    const float4* px = reinterpret_cast<const float4*>(xblk + (size_t)srow * DD + kc * BK + skh);
    const float4* pw = reinterpret_cast<const float4*>(wblk + (size_t)srow * DD + kc * BK + skh);
#pragma unroll
    for (int u = 0; u < 4; u++) { rx[u] = px[u]; rw[u] = pw[u]; }
}

__device__ __forceinline__ void stage_sts(float* xd, float* wd,
                                          const float* s_g, const float* s_b,
                                          int srow, int skh, int kc,
                                          float mu, float rstd,
                                          const float4 rx[4], const float4 rw[4]) {
#pragma unroll
    for (int u = 0; u < 4; u++) {
        float xv[4] = {rx[u].x, rx[u].y, rx[u].z, rx[u].w};
        float wv[4] = {rw[u].x, rw[u].y, rw[u].z, rw[u].w};
#pragma unroll
        for (int c = 0; c < 4; c++) {
            int kl = skh + u * 4 + c;
            int kg = kc * BK + kl;
            // LayerNorm applied at staging time (x stays raw in gmem/L2)
            xd[kl * XSTR + srow] = fmaf((xv[c] - mu) * rstd, s_g[kg], s_b[kg]);
            wd[kl * WSTR + srow] = wv[c];
        }
    }
}

__global__ void __launch_bounds__(NTHREADS)
mamba_fused(const float* __restrict__ x,
            const float* __restrict__ Wp,    // [EE][DD]
            const float* __restrict__ bp,    // [EE]
            const float* __restrict__ Wst,   // [NS][EE]
            const float* __restrict__ bst,   // [NS]
            const float* __restrict__ Wo,    // [DD][NS]
            const float* __restrict__ bo,    // [DD]
            const float* __restrict__ istate,// [NS]
            const float* __restrict__ gamma, // [DD]
            const float* __restrict__ beta,  // [DD]
            float* __restrict__ out)
{
    extern __shared__ float sm[];
    float* s_mu   = sm + OFF_MU;
    float* s_rstd = sm + OFF_RSTD;
    float* s_su   = sm + OFF_SU;     // [BT][NS], later reused for cs
    float* s_g    = sm + OFF_GAMMA;
    float* s_b    = sm + OFF_BETA;
    float* s_xs   = sm + OFF_XS;     // [2][BK][XSTR]
    float* s_ws   = sm + OFF_WS;     // [2][BK][WSTR]

    const int tid = threadIdx.x;
    const int t0  = blockIdx.x * BT;

    // ---------------- Phase 0: LN stats + stage gamma/beta + zero su ----------------
    {
        int tk = tid >> 1, half = tid & 1;
        const float4* xr = reinterpret_cast<const float4*>(
            x + (size_t)(t0 + tk) * DD + half * (DD / 2));
        float s = 0.f, ss = 0.f;
#pragma unroll 4
        for (int i = 0; i < DD / 8; i++) {   // 128 float4 per half-row
            float4 v = xr[i];
            s  += v.x + v.y + v.z + v.w;
            ss += v.x * v.x + v.y * v.y + v.z * v.z + v.w * v.w;
        }
        s  += __shfl_xor_sync(0xFFFFFFFFu, s, 1);
        ss += __shfl_xor_sync(0xFFFFFFFFu, ss, 1);
        if (half == 0) {
            float mu  = s * (1.0f / DD);
            float var = ss * (1.0f / DD) - mu * mu;
            s_mu[tk]   = mu;
            s_rstd[tk] = rsqrtf(var + EPS);
        }
        reinterpret_cast<float4*>(s_g)[tid]  = reinterpret_cast<const float4*>(gamma)[tid];
        reinterpret_cast<float4*>(s_b)[tid]  = reinterpret_cast<const float4*>(beta)[tid];
        reinterpret_cast<float4*>(s_su)[tid] = make_float4(0.f, 0.f, 0.f, 0.f);
    }
    __syncthreads();

    // ---------------- Phase 1: proj GEMM + silu + state reduction ----------------
    const int ty   = tid >> 4;        // token group 0..15 (8 tokens each)
    const int tx   = tid & 15;        // e group 0..15 (8 e's each)
    const int srow = tid >> 1;        // staging row 0..127
    const int skh  = (tid & 1) * 16;  // staging k half-offset

    const float* xblk = x + (size_t)t0 * DD;

    for (int et = 0; et < EE / BE; et++) {
        const float* wblk = Wp + (size_t)(et * BE) * DD;
        float acc[8][8];
#pragma unroll
        for (int i = 0; i < 8; i++)
#pragma unroll
            for (int j = 0; j < 8; j++) acc[i][j] = 0.f;

        float4 rx[4], rw[4];
        const float mu_s   = s_mu[srow];
        const float rstd_s = s_rstd[srow];

        // preload + stage chunk 0 into buffer 0
        stage_ldg(xblk, wblk, srow, skh, 0, rx, rw);
        stage_sts(s_xs, s_ws, s_g, s_b, srow, skh, 0, mu_s, rstd_s, rx, rw);
        __syncthreads();

#pragma unroll 1
        for (int kc = 0; kc < DD / BK; kc++) {
            const int cur = kc & 1;
            if (kc + 1 < DD / BK)
                stage_ldg(xblk, wblk, srow, skh, kc + 1, rx, rw);

            const float* xsb = s_xs + cur * (BK * XSTR);
            const float* wsb = s_ws + cur * (BK * WSTR);
#pragma unroll 4
            for (int k = 0; k < BK; k++) {
                float4 a0 = *reinterpret_cast<const float4*>(xsb + k * XSTR + ty * 8);
                float4 a1 = *reinterpret_cast<const float4*>(xsb + k * XSTR + ty * 8 + 4);
                float4 b0 = *reinterpret_cast<const float4*>(wsb + k * WSTR + tx * 8);
                float4 b1 = *reinterpret_cast<const float4*>(wsb + k * WSTR + tx * 8 + 4);
                float a[8] = {a0.x, a0.y, a0.z, a0.w, a1.x, a1.y, a1.z, a1.w};
                float b[8] = {b0.x, b0.y, b0.z, b0.w, b1.x, b1.y, b1.z, b1.w};
#pragma unroll
                for (int i = 0; i < 8; i++)
#pragma unroll
                    for (int j = 0; j < 8; j++)
                        acc[i][j] = fmaf(a[i], b[j], acc[i][j]);
            }
            __syncthreads();
            if (kc + 1 < DD / BK) {
                stage_sts(s_xs + (1 - cur) * (BK * XSTR),
                          s_ws + (1 - cur) * (BK * WSTR),
                          s_g, s_b, srow, skh, kc + 1, mu_s, rstd_s, rx, rw);
                __syncthreads();
            }
        }

        // epilogue: bias + silu (in place), then fold into su via warp reduce
        const int ebase = et * BE + tx * 8;
        float bpv[8];
#pragma unroll
        for (int j = 0; j < 8; j++) bpv[j] = bp[ebase + j];
#pragma unroll
        for (int i = 0; i < 8; i++)
#pragma unroll
            for (int j = 0; j < 8; j++)
                acc[i][j] = silu_f(acc[i][j] + bpv[j]);

#pragma unroll
        for (int n = 0; n < NS; n++) {
            float wv[8];
#pragma unroll
            for (int j = 0; j < 8; j++) wv[j] = Wst[n * EE + ebase + j];
#pragma unroll
            for (int i = 0; i < 8; i++) {
                float r = 0.f;
#pragma unroll
                for (int j = 0; j < 8; j++) r = fmaf(acc[i][j], wv[j], r);
                // reduce across 16 tx lanes (xor 8,4,2,1 stays within 16-lane half)
                r += __shfl_xor_sync(0xFFFFFFFFu, r, 8);
                r += __shfl_xor_sync(0xFFFFFFFFu, r, 4);
                r += __shfl_xor_sync(0xFFFFFFFFu, r, 2);
                r += __shfl_xor_sync(0xFFFFFFFFu, r, 1);
                if (tx == 0)
                    s_su[(ty * 8 + i) * NS + n] += r;  // unique writer per (t,n)
            }
        }
    }
    __syncthreads();

    // ---------------- Phase 2: current_state = silu(init + b_state + su) ----------------
#pragma unroll
    for (int q = 0; q < 4; q++) {
        int idx = tid * 4 + q;                 // 0..1023 over [BT][NS]
        int n   = idx & 7;
        s_su[idx] = silu_f(s_su[idx] + bst[n] + istate[n]);
    }
    __syncthreads();

    // ---------------- Phase 3: out = x + cs @ W_outT + b_out ----------------
    const float4* x4 = reinterpret_cast<const float4*>(x + (size_t)t0 * DD);
    float4*       o4 = reinterpret_cast<float4*>(out + (size_t)t0 * DD);
    for (int idx = tid; idx < BT * (DD / 4); idx += NTHREADS) {
        int t = idx >> 8;            // DD/4 = 256 float4 per token
        int c = idx & 255;
        float4 xv  = x4[idx];
        float4 cs0 = *reinterpret_cast<const float4*>(s_su + t * NS);
        float4 cs1 = *reinterpret_cast<const float4*>(s_su + t * NS + 4);
        float xin[4] = {xv.x, xv.y, xv.z, xv.w};
        float ov[4];
        int d0 = c * 4;
#pragma unroll
        for (int dd = 0; dd < 4; dd++) {
            int d = d0 + dd;
            const float4* wo = reinterpret_cast<const float4*>(Wo + (size_t)d * NS);
            float4 w0 = wo[0], w1 = wo[1];
            float o = bo[d];
            o = fmaf(cs0.x, w0.x, o); o = fmaf(cs0.y, w0.y, o);
            o = fmaf(cs0.z, w0.z, o); o = fmaf(cs0.w, w0.w, o);
            o = fmaf(cs1.x, w1.x, o); o = fmaf(cs1.y, w1.y, o);
            o = fmaf(cs1.z, w1.z, o); o = fmaf(cs1.w, w1.w, o);
            ov[dd] = xin[dd] + o;
        }
        o4[idx] = make_float4(ov[0], ov[1], ov[2], ov[3]);
    }
}

extern "C" void kernel_launch(void* const* d_in, const int* in_sizes, int n_in,
                              void* d_out, int out_size) {
    (void)in_sizes; (void)n_in; (void)out_size;
    const float* x      = (const float*)d_in[0];
    const float* Wp     = (const float*)d_in[1];
    const float* bp     = (const float*)d_in[2];
    const float* Wst    = (const float*)d_in[3];
    const float* bst    = (const float*)d_in[4];
    const float* Wo     = (const float*)d_in[5];
    const float* bo     = (const float*)d_in[6];
    const float* istate = (const float*)d_in[7];
    const float* gamma  = (const float*)d_in[8];
    const float* beta   = (const float*)d_in[9];

    const size_t smem = SMEM_FLOATS * sizeof(float);   // 80896 B
    cudaFuncSetAttribute(mamba_fused,
                         cudaFuncAttributeMaxDynamicSharedMemorySize, (int)smem);
    mamba_fused<<<TT / BT, NTHREADS, smem>>>(x, Wp, bp, Wst, bst, Wo, bo,
                                             istate, gamma, beta, (float*)d_out);
}

// round 4
// speedup vs baseline: 2.5091x; 2.5091x over previous
#include <cuda_runtime.h>
#include <cstdint>

// ---------------- problem constants ----------------
#define TT 50176
#define DD 1024
#define EE 2048
#define NS 8
#define EPS 1e-5f

#define NBLK 392            // token blocks of 128
#define NET 16              // e tiles of 128
#define NKC 64              // K chunks of 16
#define NCHUNK (NET * NKC)  // 1024
#define CH_FLOATS 2048      // floats per packed A or B chunk (128x16)
#define NSTAGE 4
#define SMEM_FLOATS (NSTAGE * 4096 + 1024)   // stages + s_su = 17408 fl = 69632 B

// ---------------- scratch (device globals; no allocation) ----------------
__device__ float g_xnt[(size_t)NBLK * NKC * CH_FLOATS];  // 205.5 MB, frag-packed xn (tf32)
__device__ float g_wpt[(size_t)NET * NKC * CH_FLOATS];   // 8 MB,    frag-packed Wp (tf32)

// ---------------- helpers ----------------
__device__ __forceinline__ float tf32_rna(float v) {
    uint32_t u; asm("cvt.rna.tf32.f32 %0, %1;" : "=r"(u) : "f"(v));
    return __uint_as_float(u);
}
__device__ __forceinline__ float silu_f(float v) { return v * (1.0f / (1.0f + __expf(-v))); }
__device__ __forceinline__ uint32_t smem_u32(const void* p) {
    uint32_t a;
    asm("{ .reg .u64 t; cvta.to.shared.u64 t, %1; cvt.u32.u64 %0, t; }" : "=r"(a) : "l"(p));
    return a;
}
#define CP_ASYNC16(dst, src) \
    asm volatile("cp.async.cg.shared.global [%0], [%1], 16;" :: "r"(dst), "l"(src))
#define CP_COMMIT() asm volatile("cp.async.commit_group;")
#define CP_WAIT(n)  asm volatile("cp.async.wait_group %0;" :: "n"(n))

__device__ __forceinline__ void mma_tf32(float d[4], const uint32_t a[4], const uint32_t b[2]) {
    asm volatile(
        "mma.sync.aligned.m16n8k8.row.col.f32.tf32.tf32.f32 "
        "{%0,%1,%2,%3}, {%4,%5,%6,%7}, {%8,%9}, {%0,%1,%2,%3};"
        : "+f"(d[0]), "+f"(d[1]), "+f"(d[2]), "+f"(d[3])
        : "r"(a[0]), "r"(a[1]), "r"(a[2]), "r"(a[3]), "r"(b[0]), "r"(b[1]));
}

// ---------------- kernel 1: LN + tf32 round + fragment packing ----------------
// A pack, per (tb,kc) chunk of 2048 floats:
//   o = (MF*2+ks)*128 + l*4 + ri ; l = g*4+r ; ri = q*2+hi
//   element: m = MF*16 + hi*8 + g ; kk = ks*8 + q*4 + r
// B pack, per (et,kc):
//   o = (NF*2+ks)*64 + l*2 + q ; l = g*4+t
//   element: n = NF*8 + g ; kk = ks*8 + q*4 + t
__global__ void __launch_bounds__(256)
prep(const float* __restrict__ x, const float* __restrict__ Wp,
     const float* __restrict__ gamma, const float* __restrict__ beta)
{
    __shared__ float s_mu[128], s_rstd[128];
    __shared__ float s_t[128 * 20];
    const int bid = blockIdx.x, tid = threadIdx.x;
    const bool isW = (bid >= NBLK);
    const float* src = isW ? Wp + (size_t)(bid - NBLK) * 128 * DD
                           : x + (size_t)bid * 128 * DD;
    float* dst = isW ? g_wpt + (size_t)(bid - NBLK) * NKC * CH_FLOATS
                     : g_xnt + (size_t)bid * NKC * CH_FLOATS;

    if (!isW) {
        int tk = tid >> 1, half = tid & 1;
        const float4* xr = reinterpret_cast<const float4*>(src + (size_t)tk * DD + half * (DD / 2));
        float s = 0.f, ss = 0.f;
#pragma unroll 4
        for (int i = 0; i < DD / 8; i++) {
            float4 v = xr[i];
            s  += v.x + v.y + v.z + v.w;
            ss += v.x * v.x + v.y * v.y + v.z * v.z + v.w * v.w;
        }
        s  += __shfl_xor_sync(0xFFFFFFFFu, s, 1);
        ss += __shfl_xor_sync(0xFFFFFFFFu, ss, 1);
        if (!half) {
            float mu = s * (1.0f / DD);
            float var = ss * (1.0f / DD) - mu * mu;
            s_mu[tk] = mu; s_rstd[tk] = rsqrtf(var + EPS);
        }
    }
    __syncthreads();

    for (int kc = 0; kc < NKC; kc++) {
        // load raw 128x16 chunk (coalesced) into padded smem
#pragma unroll
        for (int i = 0; i < 2; i++) {
            int id = i * 256 + tid;          // 0..511 float4s
            int row = id >> 2, c4 = id & 3;
            float4 v = *reinterpret_cast<const float4*>(src + (size_t)row * DD + kc * 16 + c4 * 4);
            *reinterpret_cast<float4*>(s_t + row * 20 + c4 * 4) = v;   // 80B row stride, 16B aligned
        }
        __syncthreads();
        if (isW) {
#pragma unroll
            for (int j = 0; j < 8; j++) {
                int o = j * 256 + tid;
                int MS = o >> 6, NF = MS >> 1, ks = MS & 1;
                int jj = o & 63, l = jj >> 1, q = jj & 1, g = l >> 2, t = l & 3;
                int n = NF * 8 + g, kk = ks * 8 + q * 4 + t;
                dst[(size_t)kc * CH_FLOATS + o] = tf32_rna(s_t[n * 20 + kk]);
            }
        } else {
#pragma unroll
            for (int j = 0; j < 8; j++) {
                int o = j * 256 + tid;
                int MS = o >> 7, MF = MS >> 1, ks = MS & 1;
                int l = (o >> 2) & 31, g = l >> 2, r = l & 3;
                int ri = o & 3, q = ri >> 1, hi = ri & 1;
                int m = MF * 16 + hi * 8 + g;
                int kk = ks * 8 + q * 4 + r;
                int k = kc * 16 + kk;
                float v = s_t[m * 20 + kk];
                v = fmaf((v - s_mu[m]) * s_rstd[m], gamma[k], beta[k]);
                dst[(size_t)kc * CH_FLOATS + o] = tf32_rna(v);
            }
        }
        __syncthreads();
    }
}

// ---------------- kernel 2: mma.sync GEMM + epilogue + fused tail ----------------
__global__ void __launch_bounds__(128)
mamba_mma(const float* __restrict__ x,   const float* __restrict__ bp,
          const float* __restrict__ Wst, const float* __restrict__ bst,
          const float* __restrict__ Wo,  const float* __restrict__ bo,
          const float* __restrict__ istate, float* __restrict__ out)
{
    extern __shared__ float sm[];
    float* s_su = sm + NSTAGE * 4096;     // [128][8]
    const int tid = threadIdx.x, lane = tid & 31, wid = tid >> 5;
    const int wm = wid >> 1, wn = wid & 1;          // 2x2 warp grid, 64x64 per warp
    const int tb = blockIdx.x;
    const uint32_t sb = smem_u32(sm);
    const int g = lane >> 2, t = lane & 3;

    for (int i = tid; i < 1024; i += 128) s_su[i] = 0.f;

    const float* Ab = g_xnt + (size_t)tb * NKC * CH_FLOATS;

    auto stage = [&](int c) {
        int st = c & 3, et = c >> 6, kc = c & 63;
        const float* As = Ab + (size_t)kc * CH_FLOATS;
        const float* Bs = g_wpt + ((size_t)et * NKC + kc) * CH_FLOATS;
        uint32_t d = sb + st * 16384;
#pragma unroll
        for (int i = 0; i < 4; i++) {
            int id = i * 128 + tid;
            CP_ASYNC16(d + id * 16, As + id * 4);
            CP_ASYNC16(d + 8192 + id * 16, Bs + id * 4);
        }
        CP_COMMIT();
    };
    stage(0); stage(1); stage(2);

    float acc[4][8][4];
#pragma unroll
    for (int mf = 0; mf < 4; mf++)
#pragma unroll
        for (int nf = 0; nf < 8; nf++)
#pragma unroll
            for (int r = 0; r < 4; r++) acc[mf][nf][r] = 0.f;

    for (int c = 0; c < NCHUNK; c++) {
        CP_WAIT(2);
        __syncthreads();
        if (c + 3 < NCHUNK) stage(c + 3);

        const float* As = sm + (c & 3) * 4096;
        const float* Bs = As + 2048;
#pragma unroll
        for (int ks = 0; ks < 2; ks++) {
            uint32_t a[4][4], b[8][2];
#pragma unroll
            for (int mf = 0; mf < 4; mf++) {
                float4 v = *reinterpret_cast<const float4*>(
                    As + (((wm * 4 + mf) * 2 + ks) * 128 + lane * 4));
                a[mf][0] = __float_as_uint(v.x); a[mf][1] = __float_as_uint(v.y);
                a[mf][2] = __float_as_uint(v.z); a[mf][3] = __float_as_uint(v.w);
            }
#pragma unroll
            for (int nf = 0; nf < 8; nf++) {
                float2 v = *reinterpret_cast<const float2*>(
                    Bs + (((wn * 8 + nf) * 2 + ks) * 64 + lane * 2));
                b[nf][0] = __float_as_uint(v.x); b[nf][1] = __float_as_uint(v.y);
            }
#pragma unroll
            for (int mf = 0; mf < 4; mf++)
#pragma unroll
                for (int nf = 0; nf < 8; nf++)
                    mma_tf32(acc[mf][nf], a[mf], b[nf]);
        }

        if ((c & 63) == 63) {
            const int et = c >> 6;
            // ---- epilogue: bias + silu + fold d_state reduction ----
#pragma unroll
            for (int mf = 0; mf < 4; mf++) {
                float pr0[8], pr1[8];
#pragma unroll
                for (int n = 0; n < 8; n++) { pr0[n] = 0.f; pr1[n] = 0.f; }
#pragma unroll
                for (int nf = 0; nf < 8; nf++) {
                    int col0 = et * 128 + wn * 64 + nf * 8 + 2 * t;
                    float bp0 = bp[col0], bp1 = bp[col0 + 1];
                    float s00 = silu_f(acc[mf][nf][0] + bp0);
                    float s01 = silu_f(acc[mf][nf][1] + bp1);
                    float s10 = silu_f(acc[mf][nf][2] + bp0);
                    float s11 = silu_f(acc[mf][nf][3] + bp1);
#pragma unroll
                    for (int n = 0; n < 8; n++) {
                        float w0 = Wst[n * EE + col0], w1 = Wst[n * EE + col0 + 1];
                        pr0[n] = fmaf(s00, w0, fmaf(s01, w1, pr0[n]));
                        pr1[n] = fmaf(s10, w0, fmaf(s11, w1, pr1[n]));
                    }
                }
#pragma unroll
                for (int n = 0; n < 8; n++) {
                    pr0[n] += __shfl_xor_sync(0xFFFFFFFFu, pr0[n], 1);
                    pr0[n] += __shfl_xor_sync(0xFFFFFFFFu, pr0[n], 2);
                    pr1[n] += __shfl_xor_sync(0xFFFFFFFFu, pr1[n], 1);
                    pr1[n] += __shfl_xor_sync(0xFFFFFFFFu, pr1[n], 2);
                }
                if (t == 0) {
                    int r0 = wm * 64 + mf * 16 + g;
#pragma unroll
                    for (int n = 0; n < 8; n++) {
                        atomicAdd(&s_su[r0 * 8 + n], pr0[n]);
                        atomicAdd(&s_su[(r0 + 8) * 8 + n], pr1[n]);
                    }
                }
            }
#pragma unroll
            for (int mf = 0; mf < 4; mf++)
#pragma unroll
                for (int nf = 0; nf < 8; nf++)
#pragma unroll
                    for (int r = 0; r < 4; r++) acc[mf][nf][r] = 0.f;
        }
    }
    __syncthreads();

    // current_state = silu(init + b_state + su)
    for (int i = tid; i < 1024; i += 128) {
        int n = i & 7;
        s_su[i] = silu_f(s_su[i] + bst[n] + istate[n]);
    }
    __syncthreads();

    // tail: out = x + cs @ WoT + bo
    const float4* x4 = reinterpret_cast<const float4*>(x + (size_t)tb * 128 * DD);
    float4*       o4 = reinterpret_cast<float4*>(out + (size_t)tb * 128 * DD);
    for (int idx = tid; idx < 128 * (DD / 4); idx += 128) {
        int tt = idx >> 8, cc = idx & 255;
        float4 xv  = x4[idx];
        float4 cs0 = *reinterpret_cast<const float4*>(s_su + tt * NS);
        float4 cs1 = *reinterpret_cast<const float4*>(s_su + tt * NS + 4);
        float xin[4] = {xv.x, xv.y, xv.z, xv.w};
        float ov[4];
        int d0 = cc * 4;
#pragma unroll
        for (int dd = 0; dd < 4; dd++) {
            int d = d0 + dd;
            const float4* wo = reinterpret_cast<const float4*>(Wo + (size_t)d * NS);
            float4 w0 = wo[0], w1 = wo[1];
            float o = bo[d];
            o = fmaf(cs0.x, w0.x, o); o = fmaf(cs0.y, w0.y, o);
            o = fmaf(cs0.z, w0.z, o); o = fmaf(cs0.w, w0.w, o);
            o = fmaf(cs1.x, w1.x, o); o = fmaf(cs1.y, w1.y, o);
            o = fmaf(cs1.z, w1.z, o); o = fmaf(cs1.w, w1.w, o);
            ov[dd] = xin[dd] + o;
        }
        o4[idx] = make_float4(ov[0], ov[1], ov[2], ov[3]);
    }
}

extern "C" void kernel_launch(void* const* d_in, const int* in_sizes, int n_in,
                              void* d_out, int out_size) {
    (void)in_sizes; (void)n_in; (void)out_size;
    const float* x      = (const float*)d_in[0];
    const float* Wp     = (const float*)d_in[1];
    const float* bp     = (const float*)d_in[2];
    const float* Wst    = (const float*)d_in[3];
    const float* bst    = (const float*)d_in[4];
    const float* Wo     = (const float*)d_in[5];
    const float* bo     = (const float*)d_in[6];
    const float* istate = (const float*)d_in[7];
    const float* gamma  = (const float*)d_in[8];
    const float* beta   = (const float*)d_in[9];

    prep<<<NBLK + NET, 256>>>(x, Wp, gamma, beta);

    cudaFuncSetAttribute(mamba_mma,
                         cudaFuncAttributeMaxDynamicSharedMemorySize, SMEM_FLOATS * 4);
    mamba_mma<<<NBLK, 128, SMEM_FLOATS * 4>>>(x, bp, Wst, bst, Wo, bo, istate, (float*)d_out);
}

// round 5
// speedup vs baseline: 3.2107x; 1.2796x over previous
#include <cuda_runtime.h>
#include <cstdint>

// ---------------- problem constants ----------------
#define TT 50176
#define DD 1024
#define EE 2048
#define NS 8
#define EPS 1e-5f

#define NBLK 392            // token blocks of 128
#define NET 16              // e tiles of 128
#define NKC 32              // K chunks of 32
#define NCH (NET * NKC)     // 512 chunks
#define CH 4096             // floats per packed 128x32 chunk
#define STG 3
#define SMEM_FLOATS (STG * 8192 + 1024)     // 25600 fl = 102400 B

// ---------------- scratch (device globals; no allocation) ----------------
__device__ float g_xnt[(size_t)NBLK * NKC * CH];  // frag-packed xn (tf32)
__device__ float g_wpt[(size_t)NET * NKC * CH];   // frag-packed Wp (tf32), nf pair-packed

// ---------------- helpers ----------------
__device__ __forceinline__ float tf32_rna(float v) {
    uint32_t u; asm("cvt.rna.tf32.f32 %0, %1;" : "=r"(u) : "f"(v));
    return __uint_as_float(u);
}
__device__ __forceinline__ float silu_f(float v) { return v * (1.0f / (1.0f + __expf(-v))); }
__device__ __forceinline__ uint32_t smem_u32(const void* p) {
    uint32_t a;
    asm("{ .reg .u64 t; cvta.to.shared.u64 t, %1; cvt.u32.u64 %0, t; }" : "=r"(a) : "l"(p));
    return a;
}
#define CP_ASYNC16(dst, src) \
    asm volatile("cp.async.cg.shared.global [%0], [%1], 16;" :: "r"(dst), "l"(src))
#define CP_COMMIT() asm volatile("cp.async.commit_group;")
#define CP_WAIT(n)  asm volatile("cp.async.wait_group %0;" :: "n"(n))

__device__ __forceinline__ void mma_tf32(float d[4], const uint32_t a[4],
                                         uint32_t b0, uint32_t b1) {
    asm volatile(
        "mma.sync.aligned.m16n8k8.row.col.f32.tf32.tf32.f32 "
        "{%0,%1,%2,%3}, {%4,%5,%6,%7}, {%8,%9}, {%0,%1,%2,%3};"
        : "+f"(d[0]), "+f"(d[1]), "+f"(d[2]), "+f"(d[3])
        : "r"(a[0]), "r"(a[1]), "r"(a[2]), "r"(a[3]), "r"(b0), "r"(b1));
}

// ---------------- kernel 1: LN + tf32 round + fragment packing (BK=32 chunks) ----------
// A chunk (4096 fl): o=(MF*4+ks)*128 + l*4 + ri ; l=g*4+r ; ri=q*2+hi
//   m=MF*16+hi*8+g ; kk=ks*8+q*4+r          (MF 0..7, ks 0..3)
// B chunk (4096 fl): o=(NFP*4+ks)*128 + l*4 + j ; l=g*4+t
//   n=NFP*16+(j>>1)*8+g ; kk=ks*8+(j&1)*4+t (NFP 0..7 = nf pairs)
__global__ void __launch_bounds__(256)
prep(const float* __restrict__ x, const float* __restrict__ Wp,
     const float* __restrict__ gamma, const float* __restrict__ beta)
{
    __shared__ float s_mu[128], s_rstd[128];
    __shared__ float s_t[128 * 36];
    const int bid = blockIdx.x, tid = threadIdx.x;
    const bool isW = (bid >= NBLK);
    const float* src = isW ? Wp + (size_t)(bid - NBLK) * 128 * DD
                           : x + (size_t)bid * 128 * DD;
    float* dst = isW ? g_wpt + (size_t)(bid - NBLK) * NKC * CH
                     : g_xnt + (size_t)bid * NKC * CH;

    if (!isW) {
        int tk = tid >> 1, half = tid & 1;
        const float4* xr = reinterpret_cast<const float4*>(src + (size_t)tk * DD + half * (DD / 2));
        float s = 0.f, ss = 0.f;
#pragma unroll 4
        for (int i = 0; i < DD / 8; i++) {
            float4 v = xr[i];
            s  += v.x + v.y + v.z + v.w;
            ss += v.x * v.x + v.y * v.y + v.z * v.z + v.w * v.w;
        }
        s  += __shfl_xor_sync(0xFFFFFFFFu, s, 1);
        ss += __shfl_xor_sync(0xFFFFFFFFu, ss, 1);
        if (!half) {
            float mu = s * (1.0f / DD);
            float var = ss * (1.0f / DD) - mu * mu;
            s_mu[tk] = mu; s_rstd[tk] = rsqrtf(var + EPS);
        }
    }
    __syncthreads();

    for (int kc = 0; kc < NKC; kc++) {
#pragma unroll
        for (int i = 0; i < 4; i++) {
            int id = i * 256 + tid;          // 1024 float4s = 128 rows x 8
            int row = id >> 3, c4 = id & 7;
            float4 v = *reinterpret_cast<const float4*>(src + (size_t)row * DD + kc * 32 + c4 * 4);
            *reinterpret_cast<float4*>(s_t + row * 36 + c4 * 4) = v;
        }
        __syncthreads();
        if (isW) {
#pragma unroll
            for (int j = 0; j < 16; j++) {
                int o = j * 256 + tid;
                int MS = o >> 7, NFP = MS >> 2, ks = MS & 3;
                int l = (o >> 2) & 31, g = l >> 2, t = l & 3, jj = o & 3;
                int n = NFP * 16 + (jj >> 1) * 8 + g, kk = ks * 8 + (jj & 1) * 4 + t;
                dst[(size_t)kc * CH + o] = tf32_rna(s_t[n * 36 + kk]);
            }
        } else {
#pragma unroll
            for (int j = 0; j < 16; j++) {
                int o = j * 256 + tid;
                int MS = o >> 7, MF = MS >> 2, ks = MS & 3;
                int l = (o >> 2) & 31, g = l >> 2, r = l & 3;
                int ri = o & 3, q = ri >> 1, hi = ri & 1;
                int m = MF * 16 + hi * 8 + g, kk = ks * 8 + q * 4 + r;
                int k = kc * 32 + kk;
                float v = s_t[m * 36 + kk];
                v = fmaf((v - s_mu[m]) * s_rstd[m], gamma[k], beta[k]);
                dst[(size_t)kc * CH + o] = tf32_rna(v);
            }
        }
        __syncthreads();
    }
}

// ---------------- kernel 2: mma.sync GEMM (8 warps, 64x32 tiles) + epilogue + tail ----
__global__ void __launch_bounds__(256, 2)
mamba_mma(const float* __restrict__ x,   const float* __restrict__ bp,
          const float* __restrict__ Wst, const float* __restrict__ bst,
          const float* __restrict__ Wo,  const float* __restrict__ bo,
          const float* __restrict__ istate, float* __restrict__ out)
{
    extern __shared__ float sm[];
    float* s_su = sm + STG * 8192;           // [128][8]
    const int tid = threadIdx.x, lane = tid & 31, wid = tid >> 5;
    const int wm = wid >> 2, wn = wid & 3;   // 2x4 warp grid, 64x32 per warp
    const int tb = blockIdx.x;
    const uint32_t sb = smem_u32(sm);
    const int g = lane >> 2, t = lane & 3;

    for (int i = tid; i < 1024; i += 256) s_su[i] = 0.f;

    const float* Ab = g_xnt + (size_t)tb * NKC * CH;

    auto stage = [&](int c) {
        int st = c % 3, et = c >> 5, kc = c & 31;
        const float* As = Ab + (size_t)kc * CH;
        const float* Bs = g_wpt + ((size_t)et * NKC + kc) * CH;
        uint32_t d = sb + st * 32768;
#pragma unroll
        for (int i = 0; i < 4; i++) {
            int id = i * 256 + tid;
            CP_ASYNC16(d + id * 16, As + id * 4);
            CP_ASYNC16(d + 16384 + id * 16, Bs + id * 4);
        }
        CP_COMMIT();
    };
    stage(0); stage(1);

    float acc[4][4][4];
#pragma unroll
    for (int mf = 0; mf < 4; mf++)
#pragma unroll
        for (int nf = 0; nf < 4; nf++)
#pragma unroll
            for (int r = 0; r < 4; r++) acc[mf][nf][r] = 0.f;

    for (int c = 0; c < NCH; c++) {
        CP_WAIT(1);
        __syncthreads();
        if (c + 2 < NCH) stage(c + 2);

        const float* As = sm + (c % 3) * 8192;
        const float* Bs = As + 4096;
#pragma unroll
        for (int ks = 0; ks < 4; ks++) {
            uint32_t a[4][4], b[2][4];
#pragma unroll
            for (int mf = 0; mf < 4; mf++) {
                float4 v = *reinterpret_cast<const float4*>(
                    As + (((wm * 4 + mf) * 4 + ks) * 128 + lane * 4));
                a[mf][0] = __float_as_uint(v.x); a[mf][1] = __float_as_uint(v.y);
                a[mf][2] = __float_as_uint(v.z); a[mf][3] = __float_as_uint(v.w);
            }
#pragma unroll
            for (int p = 0; p < 2; p++) {
                float4 v = *reinterpret_cast<const float4*>(
                    Bs + (((wn * 2 + p) * 4 + ks) * 128 + lane * 4));
                b[p][0] = __float_as_uint(v.x); b[p][1] = __float_as_uint(v.y);
                b[p][2] = __float_as_uint(v.z); b[p][3] = __float_as_uint(v.w);
            }
#pragma unroll
            for (int mf = 0; mf < 4; mf++)
#pragma unroll
                for (int p = 0; p < 2; p++) {
                    mma_tf32(acc[mf][p * 2],     a[mf], b[p][0], b[p][1]);
                    mma_tf32(acc[mf][p * 2 + 1], a[mf], b[p][2], b[p][3]);
                }
        }

        if ((c & 31) == 31) {
            const int et = c >> 5;
#pragma unroll
            for (int mf = 0; mf < 4; mf++) {
                float pr0[8], pr1[8];
#pragma unroll
                for (int n = 0; n < 8; n++) { pr0[n] = 0.f; pr1[n] = 0.f; }
#pragma unroll
                for (int nf = 0; nf < 4; nf++) {
                    int col0 = et * 128 + wn * 32 + nf * 8 + 2 * t;
                    float bp0 = bp[col0], bp1 = bp[col0 + 1];
                    float s00 = silu_f(acc[mf][nf][0] + bp0);
                    float s01 = silu_f(acc[mf][nf][1] + bp1);
                    float s10 = silu_f(acc[mf][nf][2] + bp0);
                    float s11 = silu_f(acc[mf][nf][3] + bp1);
#pragma unroll
                    for (int n = 0; n < 8; n++) {
                        float w0 = Wst[n * EE + col0], w1 = Wst[n * EE + col0 + 1];
                        pr0[n] = fmaf(s00, w0, fmaf(s01, w1, pr0[n]));
                        pr1[n] = fmaf(s10, w0, fmaf(s11, w1, pr1[n]));
                    }
                }
#pragma unroll
                for (int n = 0; n < 8; n++) {
                    pr0[n] += __shfl_xor_sync(0xFFFFFFFFu, pr0[n], 1);
                    pr0[n] += __shfl_xor_sync(0xFFFFFFFFu, pr0[n], 2);
                    pr1[n] += __shfl_xor_sync(0xFFFFFFFFu, pr1[n], 1);
                    pr1[n] += __shfl_xor_sync(0xFFFFFFFFu, pr1[n], 2);
                }
                if (t == 0) {
                    int r0 = wm * 64 + mf * 16 + g;
#pragma unroll
                    for (int n = 0; n < 8; n++) {
                        atomicAdd(&s_su[r0 * 8 + n], pr0[n]);
                        atomicAdd(&s_su[(r0 + 8) * 8 + n], pr1[n]);
                    }
                }
            }
#pragma unroll
            for (int mf = 0; mf < 4; mf++)
#pragma unroll
                for (int nf = 0; nf < 4; nf++)
#pragma unroll
                    for (int r = 0; r < 4; r++) acc[mf][nf][r] = 0.f;
        }
    }
    __syncthreads();

    // current_state = silu(init + b_state + su)
    for (int i = tid; i < 1024; i += 256) {
        int n = i & 7;
        s_su[i] = silu_f(s_su[i] + bst[n] + istate[n]);
    }
    __syncthreads();

    // tail: out = x + cs @ WoT + bo
    const float4* x4 = reinterpret_cast<const float4*>(x + (size_t)tb * 128 * DD);
    float4*       o4 = reinterpret_cast<float4*>(out + (size_t)tb * 128 * DD);
    for (int idx = tid; idx < 128 * (DD / 4); idx += 256) {
        int tt = idx >> 8, cc = idx & 255;
        float4 xv  = x4[idx];
        float4 cs0 = *reinterpret_cast<const float4*>(s_su + tt * NS);
        float4 cs1 = *reinterpret_cast<const float4*>(s_su + tt * NS + 4);
        float xin[4] = {xv.x, xv.y, xv.z, xv.w};
        float ov[4];
        int d0 = cc * 4;
#pragma unroll
        for (int dd = 0; dd < 4; dd++) {
            int d = d0 + dd;
            const float4* wo = reinterpret_cast<const float4*>(Wo + (size_t)d * NS);
            float4 w0 = wo[0], w1 = wo[1];
            float o = bo[d];
            o = fmaf(cs0.x, w0.x, o); o = fmaf(cs0.y, w0.y, o);
            o = fmaf(cs0.z, w0.z, o); o = fmaf(cs0.w, w0.w, o);
            o = fmaf(cs1.x, w1.x, o); o = fmaf(cs1.y, w1.y, o);
            o = fmaf(cs1.z, w1.z, o); o = fmaf(cs1.w, w1.w, o);
            ov[dd] = xin[dd] + o;
        }
        o4[idx] = make_float4(ov[0], ov[1], ov[2], ov[3]);
    }
}

extern "C" void kernel_launch(void* const* d_in, const int* in_sizes, int n_in,
                              void* d_out, int out_size) {
    (void)in_sizes; (void)n_in; (void)out_size;
    const float* x      = (const float*)d_in[0];
    const float* Wp     = (const float*)d_in[1];
    const float* bp     = (const float*)d_in[2];
    const float* Wst    = (const float*)d_in[3];
    const float* bst    = (const float*)d_in[4];
    const float* Wo     = (const float*)d_in[5];
    const float* bo     = (const float*)d_in[6];
    const float* istate = (const float*)d_in[7];
    const float* gamma  = (const float*)d_in[8];
    const float* beta   = (const float*)d_in[9];

    prep<<<NBLK + NET, 256>>>(x, Wp, gamma, beta);

    cudaFuncSetAttribute(mamba_mma,
                         cudaFuncAttributeMaxDynamicSharedMemorySize, SMEM_FLOATS * 4);
    mamba_mma<<<NBLK, 256, SMEM_FLOATS * 4>>>(x, bp, Wst, bst, Wo, bo, istate, (float*)d_out);
}